// round 10
// baseline (speedup 1.0000x reference)
#include <cuda_runtime.h>
#include <cuda_bf16.h>
#include <cstdint>
#include <cstddef>

#define BATCH 4
#define SEQ   2048
#define DIM   1024
#define NQKV  3072
#define SCALE 0.03125f   // 1024^-0.5

// Scratch (static device globals — allocation-free per harness rules)
__device__ float g_Q [(size_t)BATCH * SEQ * DIM];   // [b*t, d]
__device__ float g_K [(size_t)BATCH * SEQ * DIM];   // [b*t, d]
__device__ float g_Vt[(size_t)BATCH * DIM * SEQ];   // [b, d, t] (transposed V)
__device__ float g_S [(size_t)BATCH * SEQ * SEQ];   // [b, t, t]

// ---------------------------------------------------------------------------
// helpers
// ---------------------------------------------------------------------------
__device__ __forceinline__ uint32_t smem_u32(const void* p) {
    uint32_t a;
    asm("{ .reg .u64 t; cvta.to.shared.u64 t, %1; cvt.u32.u64 %0, t; }"
        : "=r"(a) : "l"(p));
    return a;
}

__device__ __forceinline__ void ldm4(uint32_t addr, uint32_t& r0, uint32_t& r1,
                                     uint32_t& r2, uint32_t& r3) {
    asm volatile("ldmatrix.sync.aligned.m8n8.x4.shared.b16 {%0,%1,%2,%3}, [%4];"
                 : "=r"(r0), "=r"(r1), "=r"(r2), "=r"(r3) : "r"(addr));
}

__device__ __forceinline__ void mma16816(float* d, const uint32_t* a, const uint32_t* b) {
    asm volatile(
        "mma.sync.aligned.m16n8k16.row.col.f32.bf16.bf16.f32 "
        "{%0,%1,%2,%3}, {%4,%5,%6,%7}, {%8,%9}, {%0,%1,%2,%3};"
        : "+f"(d[0]), "+f"(d[1]), "+f"(d[2]), "+f"(d[3])
        : "r"(a[0]), "r"(a[1]), "r"(a[2]), "r"(a[3]), "r"(b[0]), "r"(b[1]));
}

// smem geometry: rows padded to 40 bf16 (80B) — conflict-free for ldmatrix
#define ROWB        80
#define MAT_BYTES   (128 * ROWB)                 // 10240 B (128 x 32 bf16 tile)
#define STAGE_BYTES (4 * MAT_BYTES)              // Ah | Al | Bh | Bl = 40960 B
#define SMEM_BYTES  (2 * STAGE_BYTES)            // 81920 B; 2 CTAs = 160 KB/SM

// ---------------------------------------------------------------------------
// Quarter staging (128 threads): 64 rows x 32 k fp32 = 4 x 16B chunks/thread.
// fidx = t + j*128, r = fidx>>3 (0..63), c = fidx&7 — coalesced (8 thr/row).
// ---------------------------------------------------------------------------
__device__ __forceinline__ void q_load(float4* v, const float* __restrict__ M,
                                       int K, int rowbase, int kb, int t) {
#pragma unroll
    for (int j = 0; j < 4; j++) {
        const int fidx = t + j * 128;
        const int r = fidx >> 3, c = fidx & 7;
        v[j] = *(const float4*)(M + (size_t)(rowbase + r) * K + kb + c * 4);
    }
}

__device__ __forceinline__ void cvt_st(const float4 v, uint32_t s_hi, uint32_t s_lo,
                                       uint32_t off) {
    uint32_t h0, h1, l0, l1;
    asm("cvt.rn.satfinite.bf16x2.f32 %0, %1, %2;" : "=r"(h0) : "f"(v.y), "f"(v.x));
    asm("cvt.rn.satfinite.bf16x2.f32 %0, %1, %2;" : "=r"(h1) : "f"(v.w), "f"(v.z));
    const float r0 = v.x - __uint_as_float(h0 << 16);
    const float r1 = v.y - __uint_as_float(h0 & 0xffff0000u);
    const float r2 = v.z - __uint_as_float(h1 << 16);
    const float r3 = v.w - __uint_as_float(h1 & 0xffff0000u);
    asm("cvt.rn.satfinite.bf16x2.f32 %0, %1, %2;" : "=r"(l0) : "f"(r1), "f"(r0));
    asm("cvt.rn.satfinite.bf16x2.f32 %0, %1, %2;" : "=r"(l1) : "f"(r3), "f"(r2));
    asm volatile("st.shared.v2.u32 [%0], {%1, %2};" :: "r"(s_hi + off), "r"(h0), "r"(h1));
    asm volatile("st.shared.v2.u32 [%0], {%1, %2};" :: "r"(s_lo + off), "r"(l0), "r"(l1));
}

__device__ __forceinline__ void q_store(const float4* v, uint32_t s_hi, uint32_t s_lo,
                                        int rowbase, int t) {
#pragma unroll
    for (int j = 0; j < 4; j++) {
        const int fidx = t + j * 128;
        const int r = fidx >> 3, c = fidx & 7;
        cvt_st(v[j], s_hi, s_lo, (uint32_t)((rowbase + r) * ROWB + c * 8));
    }
}

// ---------------------------------------------------------------------------
// bf16-split tensor-core GEMM: C[128,128] = A[M,K] * B[N,K]^T  (both K-major)
// 4 warps (warp tile 64x64), 2 CTAs/SM. Term-reordered MMA (dep distance 8).
// Quarter-staged prefetch (16 regs) woven through the unrolled compute.
// MODE 0: X @ W^T  -> scatter to g_Q / g_K / g_Vt(transposed)
// MODE 1: Q @ K^T * scale -> g_S   (per batch)
// MODE 2: P @ Vt^T -> out          (per batch)
// ---------------------------------------------------------------------------
template <int MODE>
__global__ __launch_bounds__(128) void mma_gemm(const float* __restrict__ X,
                                                const float* __restrict__ W,
                                                float* __restrict__ Out) {
    extern __shared__ char smem[];
    const uint32_t sm = smem_u32(smem);
    const int t = threadIdx.x;
    const int wid = t >> 5;
    const int l = t & 31;
    const int z = blockIdx.z;

    const float* A;
    const float* B;
    float* C = nullptr;
    int K;
    if (MODE == 0) { A = X; B = W; K = DIM; }
    else if (MODE == 1) {
        A = g_Q + (size_t)z * SEQ * DIM;
        B = g_K + (size_t)z * SEQ * DIM;
        C = g_S + (size_t)z * SEQ * SEQ;
        K = DIM;
    } else {
        A = g_S  + (size_t)z * SEQ * SEQ;
        B = g_Vt + (size_t)z * DIM * SEQ;
        C = Out  + (size_t)z * SEQ * DIM;
        K = SEQ;
    }

    const int row0 = blockIdx.y * 128;
    const int col0 = blockIdx.x * 128;
    const int KI = K / 32;

    const int wm = (wid >> 1) * 64;     // warp M offset (2x2 warp grid)
    const int wn = (wid & 1) * 64;      // warp N offset (64-wide)

    const int a_row = l & 15;
    const int a_koff = ((l >> 4) & 1) * 8;
    const int b_row = (l & 7) + ((l >> 4) & 1) * 8;
    const int b_koff = ((l >> 3) & 1) * 8;

    float acc[4][8][4];                 // 128 regs
#pragma unroll
    for (int mi = 0; mi < 4; mi++)
#pragma unroll
        for (int ni = 0; ni < 8; ni++)
#pragma unroll
            for (int j = 0; j < 4; j++) acc[mi][ni][j] = 0.0f;

    float4 pf[4];                       // quarter prefetch buffer (16 regs)

    // prologue: stage 0 (4 quarters, immediate stores)
    q_load(pf, A, K, row0,      0, t); q_store(pf, sm,                 sm + MAT_BYTES,      0, t);
    q_load(pf, A, K, row0 + 64, 0, t); q_store(pf, sm,                 sm + MAT_BYTES,     64, t);
    q_load(pf, B, K, col0,      0, t); q_store(pf, sm + 2 * MAT_BYTES, sm + 3 * MAT_BYTES,  0, t);
    q_load(pf, B, K, col0 + 64, 0, t); q_store(pf, sm + 2 * MAT_BYTES, sm + 3 * MAT_BYTES, 64, t);
    __syncthreads();

    for (int it = 0; it < KI; it++) {
        const int s = it & 1;
        const uint32_t stg = sm + s * STAGE_BYTES;
        const uint32_t nstg = sm + (1 - s) * STAGE_BYTES;
        const bool pfv = (it + 1 < KI);
        const int kb = (it + 1) * 32;

        if (pfv) q_load(pf, A, K, row0, kb, t);        // A quarter 0

        const uint32_t sAh = stg;
        const uint32_t sAl = stg + MAT_BYTES;
        const uint32_t sBh = stg + 2 * MAT_BYTES;
        const uint32_t sBl = stg + 3 * MAT_BYTES;

#pragma unroll
        for (int k0 = 0; k0 < 32; k0 += 16) {
            uint32_t bH[8][2], bL[8][2];
#pragma unroll
            for (int nb = 0; nb < 4; nb++) {
                const uint32_t off =
                    (uint32_t)((wn + nb * 16 + b_row) * ROWB + (k0 + b_koff) * 2);
                uint32_t r0, r1, r2, r3;
                ldm4(sBh + off, r0, r1, r2, r3);
                bH[2 * nb][0] = r0; bH[2 * nb][1] = r1;
                bH[2 * nb + 1][0] = r2; bH[2 * nb + 1][1] = r3;
                ldm4(sBl + off, r0, r1, r2, r3);
                bL[2 * nb][0] = r0; bL[2 * nb][1] = r1;
                bL[2 * nb + 1][0] = r2; bL[2 * nb + 1][1] = r3;
            }
#pragma unroll
            for (int mi = 0; mi < 4; mi++) {
                // staging hooks at mi==2 (quarter latency covered by ~60 MMAs)
                if (mi == 2 && pfv) {
                    if (k0 == 0) {
                        q_store(pf, nstg, nstg + MAT_BYTES, 0, t);
                        q_load(pf, A, K, row0 + 64, kb, t);
                    } else {
                        q_store(pf, nstg + 2 * MAT_BYTES, nstg + 3 * MAT_BYTES, 0, t);
                        q_load(pf, B, K, col0 + 64, kb, t);
                    }
                }
                uint32_t aH[4], aL[4];
                const uint32_t off =
                    (uint32_t)((wm + mi * 16 + a_row) * ROWB + (k0 + a_koff) * 2);
                ldm4(sAh + off, aH[0], aH[1], aH[2], aH[3]);
                ldm4(sAl + off, aL[0], aL[1], aL[2], aL[3]);
                // term-outer ordering: same-acc writes are 8 HMMAs apart
#pragma unroll
                for (int ni = 0; ni < 8; ni++) mma16816(acc[mi][ni], aH, bH[ni]);
#pragma unroll
                for (int ni = 0; ni < 8; ni++) mma16816(acc[mi][ni], aH, bL[ni]);
#pragma unroll
                for (int ni = 0; ni < 8; ni++) mma16816(acc[mi][ni], aL, bH[ni]);
            }
            if (k0 == 0 && pfv) {
                q_store(pf, nstg, nstg + MAT_BYTES, 64, t);   // A quarter 1
                q_load(pf, B, K, col0, kb, t);                // B quarter 0
            }
        }

        if (pfv) q_store(pf, nstg + 2 * MAT_BYTES, nstg + 3 * MAT_BYTES, 64, t);
        __syncthreads();
    }

    // Epilogue: fragments -> padded smem -> (scatter) gmem
    float* Csh = (float*)smem;                     // 128 x 130 fp32 (66.6 KB)
#pragma unroll
    for (int mi = 0; mi < 4; mi++)
#pragma unroll
        for (int ni = 0; ni < 8; ni++) {
            const int r = wm + mi * 16 + (l >> 2);
            const int c = wn + ni * 8 + (l & 3) * 2;
            float d0 = acc[mi][ni][0], d1 = acc[mi][ni][1];
            float d2 = acc[mi][ni][2], d3 = acc[mi][ni][3];
            if (MODE == 1) { d0 *= SCALE; d1 *= SCALE; d2 *= SCALE; d3 *= SCALE; }
            Csh[r * 130 + c]           = d0;
            Csh[r * 130 + c + 1]       = d1;
            Csh[(r + 8) * 130 + c]     = d2;
            Csh[(r + 8) * 130 + c + 1] = d3;
        }
    __syncthreads();

    for (int i = t; i < 128 * 128; i += 128) {
        const int r = i >> 7, c = i & 127;
        const float v = Csh[r * 130 + c];
        if (MODE == 0) {
            const int grow = row0 + r;
            const int col = col0 + c;
            const int which = col % 3;             // qkv reshape (d,3)
            const int oc = col / 3;
            if (which == 0)      g_Q[(size_t)grow * DIM + oc] = v;
            else if (which == 1) g_K[(size_t)grow * DIM + oc] = v;
            else {
                const int b = grow >> 11, tt = grow & 2047;
                g_Vt[((size_t)b * DIM + oc) * SEQ + tt] = v;
            }
        } else if (MODE == 1) {
            C[(size_t)(row0 + r) * SEQ + col0 + c] = v;
        } else {
            C[(size_t)(row0 + r) * DIM + col0 + c] = v;
        }
    }
}

// ---------------------------------------------------------------------------
// Row softmax over g_S: one block (256 threads) per row of length 2048.
// ---------------------------------------------------------------------------
__global__ __launch_bounds__(256) void softmax_k() {
    float* p = g_S + (size_t)blockIdx.x * SEQ;
    const int t = threadIdx.x;
    const int lane = t & 31;
    const int warp = t >> 5;
    __shared__ float red[2][8];

    float v[8];
    float m = -1e30f;
#pragma unroll
    for (int i = 0; i < 8; i++) { v[i] = p[t + i * 256]; m = fmaxf(m, v[i]); }
#pragma unroll
    for (int off = 16; off > 0; off >>= 1)
        m = fmaxf(m, __shfl_xor_sync(0xffffffffu, m, off));
    if (lane == 0) red[0][warp] = m;
    __syncthreads();
    m = red[0][0];
#pragma unroll
    for (int w = 1; w < 8; w++) m = fmaxf(m, red[0][w]);

    float s = 0.0f;
#pragma unroll
    for (int i = 0; i < 8; i++) { v[i] = __expf(v[i] - m); s += v[i]; }
#pragma unroll
    for (int off = 16; off > 0; off >>= 1)
        s += __shfl_xor_sync(0xffffffffu, s, off);
    if (lane == 0) red[1][warp] = s;
    __syncthreads();
    s = red[1][0];
#pragma unroll
    for (int w = 1; w < 8; w++) s += red[1][w];

    const float inv = 1.0f / s;
#pragma unroll
    for (int i = 0; i < 8; i++) p[t + i * 256] = v[i] * inv;
}

// ---------------------------------------------------------------------------
extern "C" void kernel_launch(void* const* d_in, const int* in_sizes, int n_in,
                              void* d_out, int out_size) {
    const float* x = (const float*)d_in[0];    // [4, 2048, 1024]
    const float* W = (const float*)d_in[1];    // [3072, 1024]
    float* out = (float*)d_out;                // [4, 2048, 1024]

    cudaFuncSetAttribute(mma_gemm<0>, cudaFuncAttributeMaxDynamicSharedMemorySize, SMEM_BYTES);
    cudaFuncSetAttribute(mma_gemm<1>, cudaFuncAttributeMaxDynamicSharedMemorySize, SMEM_BYTES);
    cudaFuncSetAttribute(mma_gemm<2>, cudaFuncAttributeMaxDynamicSharedMemorySize, SMEM_BYTES);

    // 1) QKV projection (scatter epilogue de-interleaves into Q / K / V^T)
    mma_gemm<0><<<dim3(NQKV / 128, (BATCH * SEQ) / 128, 1), 128, SMEM_BYTES>>>(x, W, nullptr);
    // 2) scores = Q K^T * scale
    mma_gemm<1><<<dim3(SEQ / 128, SEQ / 128, BATCH), 128, SMEM_BYTES>>>(nullptr, nullptr, nullptr);
    // 3) row softmax
    softmax_k<<<dim3(BATCH * SEQ), 256>>>();
    // 4) out = P V
    mma_gemm<2><<<dim3(DIM / 128, SEQ / 128, BATCH), 128, SMEM_BYTES>>>(nullptr, nullptr, out);
}

// round 11
// speedup vs baseline: 1.1030x; 1.1030x over previous
#include <cuda_runtime.h>
#include <cuda_bf16.h>
#include <cstdint>
#include <cstddef>

#define BATCH 4
#define SEQ   2048
#define DIM   1024
#define NQKV  3072
#define SCALE 0.03125f   // 1024^-0.5

// Scratch (static device globals — allocation-free per harness rules)
__device__ float g_Q [(size_t)BATCH * SEQ * DIM];   // [b*t, d]
__device__ float g_K [(size_t)BATCH * SEQ * DIM];   // [b*t, d]
__device__ float g_Vt[(size_t)BATCH * DIM * SEQ];   // [b, d, t] (transposed V)
__device__ float g_S [(size_t)BATCH * SEQ * SEQ];   // [b, t, t]

// ---------------------------------------------------------------------------
// helpers
// ---------------------------------------------------------------------------
__device__ __forceinline__ uint32_t smem_u32(const void* p) {
    uint32_t a;
    asm("{ .reg .u64 t; cvta.to.shared.u64 t, %1; cvt.u32.u64 %0, t; }"
        : "=r"(a) : "l"(p));
    return a;
}

__device__ __forceinline__ void ldm4(uint32_t addr, uint32_t& r0, uint32_t& r1,
                                     uint32_t& r2, uint32_t& r3) {
    asm volatile("ldmatrix.sync.aligned.m8n8.x4.shared.b16 {%0,%1,%2,%3}, [%4];"
                 : "=r"(r0), "=r"(r1), "=r"(r2), "=r"(r3) : "r"(addr));
}

__device__ __forceinline__ void mma16816(float* d, const uint32_t* a, const uint32_t* b) {
    asm volatile(
        "mma.sync.aligned.m16n8k16.row.col.f32.bf16.bf16.f32 "
        "{%0,%1,%2,%3}, {%4,%5,%6,%7}, {%8,%9}, {%0,%1,%2,%3};"
        : "+f"(d[0]), "+f"(d[1]), "+f"(d[2]), "+f"(d[3])
        : "r"(a[0]), "r"(a[1]), "r"(a[2]), "r"(a[3]), "r"(b[0]), "r"(b[1]));
}

// smem geometry: rows padded to 40 bf16 (80B) — conflict-free for ldmatrix
#define ROWB        80
#define MAT_BYTES   (128 * ROWB)                 // 10240 B (128 x 32 bf16 tile)
#define STAGE_BYTES (4 * MAT_BYTES)              // Ah | Al | Bh | Bl = 40960 B
#define SMEM_BYTES  (2 * STAGE_BYTES)            // 81920 B; 2 CTAs = 160 KB/SM

// ---------------------------------------------------------------------------
// Half-stage register staging (128 threads): one 128x32 fp32 tile = 8 x 16B
// chunks per thread. fidx = t + i*128, r = fidx>>3, c = fidx&7 (coalesced,
// 8 threads per 128B row).
// ---------------------------------------------------------------------------
__device__ __forceinline__ void half_load(float4* v, const float* __restrict__ M,
                                          int K, int row0, int kb, int t) {
#pragma unroll
    for (int i = 0; i < 8; i++) {
        const int fidx = t + i * 128;
        const int r = fidx >> 3, c = fidx & 7;
        v[i] = *(const float4*)(M + (size_t)(row0 + r) * K + kb + c * 4);
    }
}

// convert one float4 chunk to hi/lo bf16x2 pairs and store (8B each)
__device__ __forceinline__ void cvt_st(const float4 v, uint32_t s_hi, uint32_t s_lo,
                                       uint32_t off) {
    uint32_t h0, h1, l0, l1;
    asm("cvt.rn.satfinite.bf16x2.f32 %0, %1, %2;" : "=r"(h0) : "f"(v.y), "f"(v.x));
    asm("cvt.rn.satfinite.bf16x2.f32 %0, %1, %2;" : "=r"(h1) : "f"(v.w), "f"(v.z));
    const float r0 = v.x - __uint_as_float(h0 << 16);
    const float r1 = v.y - __uint_as_float(h0 & 0xffff0000u);
    const float r2 = v.z - __uint_as_float(h1 << 16);
    const float r3 = v.w - __uint_as_float(h1 & 0xffff0000u);
    asm("cvt.rn.satfinite.bf16x2.f32 %0, %1, %2;" : "=r"(l0) : "f"(r1), "f"(r0));
    asm("cvt.rn.satfinite.bf16x2.f32 %0, %1, %2;" : "=r"(l1) : "f"(r3), "f"(r2));
    asm volatile("st.shared.v2.u32 [%0], {%1, %2};" :: "r"(s_hi + off), "r"(h0), "r"(h1));
    asm volatile("st.shared.v2.u32 [%0], {%1, %2};" :: "r"(s_lo + off), "r"(l0), "r"(l1));
}

__device__ __forceinline__ void half_store(const float4* v, uint32_t s_hi,
                                           uint32_t s_lo, int t) {
#pragma unroll
    for (int i = 0; i < 8; i++) {
        const int fidx = t + i * 128;
        const int r = fidx >> 3, c = fidx & 7;
        cvt_st(v[i], s_hi, s_lo, (uint32_t)(r * ROWB + c * 8));
    }
}

// ---------------------------------------------------------------------------
// bf16-split tensor-core GEMM: C[128,128] = A[M,K] * B[N,K]^T  (both K-major)
// 4 warps (warp tile 64x64), 128 threads, 2 CTAs/SM by construction.
// Split prefetch: A-half around k0=0 compute, B-half around k0=16.
// Term-outer MMA ordering: same-acc writes are 8 independent HMMAs apart.
// MODE 0: X @ W^T  -> scatter to g_Q / g_K / g_Vt(transposed)
// MODE 1: Q @ K^T * scale -> g_S   (per batch)
// MODE 2: P @ Vt^T -> out          (per batch)
// ---------------------------------------------------------------------------
template <int MODE>
__global__ __launch_bounds__(128) void mma_gemm(const float* __restrict__ X,
                                                const float* __restrict__ W,
                                                float* __restrict__ Out) {
    extern __shared__ char smem[];
    const uint32_t sm = smem_u32(smem);
    const int t = threadIdx.x;
    const int wid = t >> 5;
    const int l = t & 31;
    const int z = blockIdx.z;

    const float* A;
    const float* B;
    float* C = nullptr;
    int K;
    if (MODE == 0) { A = X; B = W; K = DIM; }
    else if (MODE == 1) {
        A = g_Q + (size_t)z * SEQ * DIM;
        B = g_K + (size_t)z * SEQ * DIM;
        C = g_S + (size_t)z * SEQ * SEQ;
        K = DIM;
    } else {
        A = g_S  + (size_t)z * SEQ * SEQ;
        B = g_Vt + (size_t)z * DIM * SEQ;
        C = Out  + (size_t)z * SEQ * DIM;
        K = SEQ;
    }

    const int row0 = blockIdx.y * 128;
    const int col0 = blockIdx.x * 128;
    const int KI = K / 32;

    const int wm = (wid >> 1) * 64;     // warp M offset (2x2 warp grid)
    const int wn = (wid & 1) * 64;      // warp N offset (64-wide)

    const int a_row = l & 15;
    const int a_koff = ((l >> 4) & 1) * 8;
    const int b_row = (l & 7) + ((l >> 4) & 1) * 8;
    const int b_koff = ((l >> 3) & 1) * 8;

    float acc[4][8][4];                 // [mi][ni][frag] — 128 regs
#pragma unroll
    for (int mi = 0; mi < 4; mi++)
#pragma unroll
        for (int ni = 0; ni < 8; ni++)
#pragma unroll
            for (int j = 0; j < 4; j++) acc[mi][ni][j] = 0.0f;

    float4 pf[8];                       // half-stage prefetch buffer

    // prologue: stage 0 (A then B halves)
    half_load(pf, A, K, row0, 0, t);
    half_store(pf, sm, sm + MAT_BYTES, t);
    half_load(pf, B, K, col0, 0, t);
    half_store(pf, sm + 2 * MAT_BYTES, sm + 3 * MAT_BYTES, t);
    __syncthreads();

    for (int it = 0; it < KI; it++) {
        const int s = it & 1;
        const uint32_t stg = sm + s * STAGE_BYTES;
        const uint32_t nstg = sm + (1 - s) * STAGE_BYTES;
        const bool pfv = (it + 1 < KI);
        const int kb = (it + 1) * 32;

        // prefetch A-half for next iter (LDG latency covered by k0=0 compute)
        if (pfv) half_load(pf, A, K, row0, kb, t);

        const uint32_t sAh = stg;
        const uint32_t sAl = stg + MAT_BYTES;
        const uint32_t sBh = stg + 2 * MAT_BYTES;
        const uint32_t sBl = stg + 3 * MAT_BYTES;

#pragma unroll
        for (int k0 = 0; k0 < 32; k0 += 16) {
            uint32_t bH[8][2], bL[8][2];
#pragma unroll
            for (int nb = 0; nb < 4; nb++) {
                const uint32_t off =
                    (uint32_t)((wn + nb * 16 + b_row) * ROWB + (k0 + b_koff) * 2);
                uint32_t r0, r1, r2, r3;
                ldm4(sBh + off, r0, r1, r2, r3);
                bH[2 * nb][0] = r0; bH[2 * nb][1] = r1;
                bH[2 * nb + 1][0] = r2; bH[2 * nb + 1][1] = r3;
                ldm4(sBl + off, r0, r1, r2, r3);
                bL[2 * nb][0] = r0; bL[2 * nb][1] = r1;
                bL[2 * nb + 1][0] = r2; bL[2 * nb + 1][1] = r3;
            }
#pragma unroll
            for (int mi = 0; mi < 4; mi++) {
                uint32_t aH[4], aL[4];
                const uint32_t off =
                    (uint32_t)((wm + mi * 16 + a_row) * ROWB + (k0 + a_koff) * 2);
                ldm4(sAh + off, aH[0], aH[1], aH[2], aH[3]);
                ldm4(sAl + off, aL[0], aL[1], aL[2], aL[3]);
                // term-outer ordering: same-acc writes 8 HMMAs apart
#pragma unroll
                for (int ni = 0; ni < 8; ni++) mma16816(acc[mi][ni], aH, bH[ni]);
#pragma unroll
                for (int ni = 0; ni < 8; ni++) mma16816(acc[mi][ni], aH, bL[ni]);
#pragma unroll
                for (int ni = 0; ni < 8; ni++) mma16816(acc[mi][ni], aL, bH[ni]);
            }

            // between the two k0 steps: store A-half, start B-half prefetch
            if (k0 == 0 && pfv) {
                half_store(pf, nstg, nstg + MAT_BYTES, t);
                half_load(pf, B, K, col0, kb, t);
            }
        }

        if (pfv) half_store(pf, nstg + 2 * MAT_BYTES, nstg + 3 * MAT_BYTES, t);
        __syncthreads();
    }

    // Epilogue: fragments -> padded smem -> (scatter) gmem
    float* Csh = (float*)smem;                     // 128 x 130 fp32 (66.6 KB)
#pragma unroll
    for (int mi = 0; mi < 4; mi++)
#pragma unroll
        for (int ni = 0; ni < 8; ni++) {
            const int r = wm + mi * 16 + (l >> 2);
            const int c = wn + ni * 8 + (l & 3) * 2;
            float d0 = acc[mi][ni][0], d1 = acc[mi][ni][1];
            float d2 = acc[mi][ni][2], d3 = acc[mi][ni][3];
            if (MODE == 1) { d0 *= SCALE; d1 *= SCALE; d2 *= SCALE; d3 *= SCALE; }
            Csh[r * 130 + c]           = d0;
            Csh[r * 130 + c + 1]       = d1;
            Csh[(r + 8) * 130 + c]     = d2;
            Csh[(r + 8) * 130 + c + 1] = d3;
        }
    __syncthreads();

    for (int i = t; i < 128 * 128; i += 128) {
        const int r = i >> 7, c = i & 127;
        const float v = Csh[r * 130 + c];
        if (MODE == 0) {
            const int grow = row0 + r;
            const int col = col0 + c;
            const int which = col % 3;             // qkv reshape (d,3)
            const int oc = col / 3;
            if (which == 0)      g_Q[(size_t)grow * DIM + oc] = v;
            else if (which == 1) g_K[(size_t)grow * DIM + oc] = v;
            else {
                const int b = grow >> 11, tt = grow & 2047;
                g_Vt[((size_t)b * DIM + oc) * SEQ + tt] = v;
            }
        } else if (MODE == 1) {
            C[(size_t)(row0 + r) * SEQ + col0 + c] = v;
        } else {
            C[(size_t)(row0 + r) * DIM + col0 + c] = v;
        }
    }
}

// ---------------------------------------------------------------------------
// Row softmax over g_S: one block (256 threads) per row of length 2048.
// ---------------------------------------------------------------------------
__global__ __launch_bounds__(256) void softmax_k() {
    float* p = g_S + (size_t)blockIdx.x * SEQ;
    const int t = threadIdx.x;
    const int lane = t & 31;
    const int warp = t >> 5;
    __shared__ float red[2][8];

    float v[8];
    float m = -1e30f;
#pragma unroll
    for (int i = 0; i < 8; i++) { v[i] = p[t + i * 256]; m = fmaxf(m, v[i]); }
#pragma unroll
    for (int off = 16; off > 0; off >>= 1)
        m = fmaxf(m, __shfl_xor_sync(0xffffffffu, m, off));
    if (lane == 0) red[0][warp] = m;
    __syncthreads();
    m = red[0][0];
#pragma unroll
    for (int w = 1; w < 8; w++) m = fmaxf(m, red[0][w]);

    float s = 0.0f;
#pragma unroll
    for (int i = 0; i < 8; i++) { v[i] = __expf(v[i] - m); s += v[i]; }
#pragma unroll
    for (int off = 16; off > 0; off >>= 1)
        s += __shfl_xor_sync(0xffffffffu, s, off);
    if (lane == 0) red[1][warp] = s;
    __syncthreads();
    s = red[1][0];
#pragma unroll
    for (int w = 1; w < 8; w++) s += red[1][w];

    const float inv = 1.0f / s;
#pragma unroll
    for (int i = 0; i < 8; i++) p[t + i * 256] = v[i] * inv;
}

// ---------------------------------------------------------------------------
extern "C" void kernel_launch(void* const* d_in, const int* in_sizes, int n_in,
                              void* d_out, int out_size) {
    const float* x = (const float*)d_in[0];    // [4, 2048, 1024]
    const float* W = (const float*)d_in[1];    // [3072, 1024]
    float* out = (float*)d_out;                // [4, 2048, 1024]

    cudaFuncSetAttribute(mma_gemm<0>, cudaFuncAttributeMaxDynamicSharedMemorySize, SMEM_BYTES);
    cudaFuncSetAttribute(mma_gemm<1>, cudaFuncAttributeMaxDynamicSharedMemorySize, SMEM_BYTES);
    cudaFuncSetAttribute(mma_gemm<2>, cudaFuncAttributeMaxDynamicSharedMemorySize, SMEM_BYTES);

    // 1) QKV projection (scatter epilogue de-interleaves into Q / K / V^T)
    mma_gemm<0><<<dim3(NQKV / 128, (BATCH * SEQ) / 128, 1), 128, SMEM_BYTES>>>(x, W, nullptr);
    // 2) scores = Q K^T * scale
    mma_gemm<1><<<dim3(SEQ / 128, SEQ / 128, BATCH), 128, SMEM_BYTES>>>(nullptr, nullptr, nullptr);
    // 3) row softmax
    softmax_k<<<dim3(BATCH * SEQ), 256>>>();
    // 4) out = P V
    mma_gemm<2><<<dim3(DIM / 128, SEQ / 128, BATCH), 128, SMEM_BYTES>>>(nullptr, nullptr, out);
}